// round 1
// baseline (speedup 1.0000x reference)
#include <cuda_runtime.h>

// Problem constants
#define CIN      32
#define COUT     64
#define OUT_DIM  1024
#define KP       4
#define DLEN     4096            // OUT_DIM * KP
#define BSZ      16
#define P_TILE   8               // patches per CTA
#define NTHREADS 512             // 16 warps: warp -> 4 o's; lane = (b_grp<<3)|p_local
#define SMEM_BYTES (BSZ * CIN * P_TILE * KP * 4)   // 64 KB

// Packed dual-FMA: only reachable via PTX fma.rn.f32x2 (ptxas won't auto-fuse).
__device__ __forceinline__ unsigned long long ffma2(unsigned long long a,
                                                    unsigned long long b,
                                                    unsigned long long c) {
    unsigned long long d;
    asm("fma.rn.f32x2 %0, %1, %2, %3;" : "=l"(d) : "l"(a), "l"(b), "l"(c));
    return d;
}

__global__ void __launch_bounds__(NTHREADS, 1)
lc1d_kernel(const float* __restrict__ x, const float* __restrict__ w,
            float* __restrict__ out) {
    extern __shared__ float xs[];   // layout: [b][c][32 floats] -> b*1024 + c*32 + d

    const int tid = threadIdx.x;
    const int p0  = blockIdx.x * P_TILE;

    // ---- Cooperative stage of x slice: 16b x 32c x 32d floats = 4096 float4 ----
    {
        const float4* xg  = reinterpret_cast<const float4*>(x);
        float4*       xs4 = reinterpret_cast<float4*>(xs);
#pragma unroll
        for (int r = 0; r < 8; ++r) {
            int idx = tid + r * NTHREADS;      // 0..4095
            int q = idx & 7;                   // float4 within 32-float row
            int c = (idx >> 3) & 31;
            int b = idx >> 8;
            // global float4 index: (b*131072 + c*4096 + p0*4)/4 + q
            xs4[idx] = xg[b * 32768 + c * 1024 + p0 + q];
            // smem float4 index b*256 + c*8 + q == idx
        }
    }
    __syncthreads();

    // ---- Thread mapping ----
    const int lane = tid & 31;
    const int p_l  = lane & 7;            // lanes 0..7: consecutive patches (contiguous LDS)
    const int b0   = (lane >> 3) * 4;     // 4 batch groups per warp
    const int o0   = (tid >> 5) * 4;      // warp id -> 4 output channels

    const float* wbase = w + (size_t)o0 * (CIN * DLEN) + (size_t)(p0 + p_l) * KP;
    const float* xsb   = xs + b0 * 1024 + p_l * 4;

    unsigned long long acc[4][4];         // [b][o] packed f32x2 accumulators
#pragma unroll
    for (int i = 0; i < 4; ++i)
#pragma unroll
        for (int j = 0; j < 4; ++j) acc[i][j] = 0ULL;

#pragma unroll 8
    for (int c = 0; c < CIN; ++c) {
        // w[o0+j, c, 4p..4p+3]  (LDG.128, one 128B line per warp per j: lanes
        // p0..p7 contiguous, b-groups broadcast)
        ulonglong2 wv[4];
#pragma unroll
        for (int j = 0; j < 4; ++j)
            wv[j] = *reinterpret_cast<const ulonglong2*>(
                wbase + (size_t)j * (CIN * DLEN) + c * DLEN);

#pragma unroll
        for (int i = 0; i < 4; ++i) {
            // x[b0+i, c, 4p..4p+3] from smem (LDS.128, phase-contiguous)
            ulonglong2 xv = *reinterpret_cast<const ulonglong2*>(xsb + i * 1024 + c * 32);
#pragma unroll
            for (int j = 0; j < 4; ++j) {
                acc[i][j] = ffma2(wv[j].x, xv.x, acc[i][j]);   // k0,k1
                acc[i][j] = ffma2(wv[j].y, xv.y, acc[i][j]);   // k2,k3
            }
        }
    }

    // ---- Epilogue ----
    const float scale = 0.17677669529663687f;   // 1/sqrt(32)
    const int p = p0 + p_l;
#pragma unroll
    for (int i = 0; i < 4; ++i)
#pragma unroll
        for (int j = 0; j < 4; ++j) {
            float2 v = *reinterpret_cast<float2*>(&acc[i][j]);
            out[(b0 + i) * (COUT * OUT_DIM) + (o0 + j) * OUT_DIM + p] =
                (v.x + v.y) * scale;
        }
}

extern "C" void kernel_launch(void* const* d_in, const int* in_sizes, int n_in,
                              void* d_out, int out_size) {
    const float* x = (const float*)d_in[0];
    const float* w = (const float*)d_in[1];
    float* out = (float*)d_out;

    // 64 KB dynamic smem (> 48 KB default). Non-stream API; idempotent; legal
    // during graph capture — called unconditionally every launch (no static guards).
    cudaFuncSetAttribute(lc1d_kernel, cudaFuncAttributeMaxDynamicSharedMemorySize,
                         SMEM_BYTES);

    lc1d_kernel<<<OUT_DIM / P_TILE, NTHREADS, SMEM_BYTES>>>(x, w, out);
}

// round 2
// speedup vs baseline: 1.0411x; 1.0411x over previous
#include <cuda_runtime.h>

// Problem constants
#define CIN      32
#define COUT     64
#define OUT_DIM  1024
#define KP       4
#define DLEN     4096            // OUT_DIM * KP
#define BSZ      16
#define P_TILE   8               // patches per CTA
#define NTHREADS 512             // 16 warps: warp -> 4 o's; lane = (b_grp<<3)|p_local
#define SMEM_BYTES (BSZ * CIN * P_TILE * KP * 4)   // 64 KB
#define NBUF     3               // w prefetch distance (ring buffers)

// Packed dual-FMA: only reachable via PTX fma.rn.f32x2 (ptxas won't auto-fuse).
__device__ __forceinline__ unsigned long long ffma2(unsigned long long a,
                                                    unsigned long long b,
                                                    unsigned long long c) {
    unsigned long long d;
    asm("fma.rn.f32x2 %0, %1, %2, %3;" : "=l"(d) : "l"(a), "l"(b), "l"(c));
    return d;
}

__global__ void __launch_bounds__(NTHREADS, 1)
lc1d_kernel(const float* __restrict__ x, const float* __restrict__ w,
            float* __restrict__ out) {
    extern __shared__ float xs[];   // layout: [b][c][32 floats] -> b*1024 + c*32 + d

    const int tid = threadIdx.x;
    const int p0  = blockIdx.x * P_TILE;

    // ---- Cooperative stage of x slice: 16b x 32c x 32d floats = 4096 float4 ----
    {
        const float4* xg  = reinterpret_cast<const float4*>(x);
        float4*       xs4 = reinterpret_cast<float4*>(xs);
#pragma unroll
        for (int r = 0; r < 8; ++r) {
            int idx = tid + r * NTHREADS;      // 0..4095
            int q = idx & 7;                   // float4 within 32-float row
            int c = (idx >> 3) & 31;
            int b = idx >> 8;
            xs4[idx] = xg[b * 32768 + c * 1024 + p0 + q];
        }
    }

    // ---- Thread mapping ----
    const int lane = tid & 31;
    const int p_l  = lane & 7;            // lanes 0..7: consecutive patches (contiguous LDG/LDS)
    const int b0   = (lane >> 3) * 4;     // 4 batch groups per warp
    const int o0   = (tid >> 5) * 4;      // warp id -> 4 output channels

    // Per-j w row pointers; c offsets become LDG immediates after full unroll.
    const float* wr0 = w + (size_t)(o0 + 0) * (CIN * DLEN) + (p0 + p_l) * KP;
    const float* wr1 = wr0 + (size_t)(CIN * DLEN);
    const float* wr2 = wr1 + (size_t)(CIN * DLEN);
    const float* wr3 = wr2 + (size_t)(CIN * DLEN);
    const float* xsb = xs + b0 * 1024 + p_l * 4;

    // ---- w prefetch ring: NBUF c-iterations deep ----
    ulonglong2 wbuf[NBUF][4];
#pragma unroll
    for (int c = 0; c < NBUF; ++c) {
        wbuf[c][0] = *reinterpret_cast<const ulonglong2*>(wr0 + c * DLEN);
        wbuf[c][1] = *reinterpret_cast<const ulonglong2*>(wr1 + c * DLEN);
        wbuf[c][2] = *reinterpret_cast<const ulonglong2*>(wr2 + c * DLEN);
        wbuf[c][3] = *reinterpret_cast<const ulonglong2*>(wr3 + c * DLEN);
    }

    __syncthreads();   // x staging complete (w prefetches already in flight)

    unsigned long long acc[4][4];         // [b][o] packed f32x2 accumulators
#pragma unroll
    for (int i = 0; i < 4; ++i)
#pragma unroll
        for (int j = 0; j < 4; ++j) acc[i][j] = 0ULL;

#pragma unroll
    for (int c = 0; c < CIN; ++c) {
        const int m = c % NBUF;

        // x for this c (LDS.128, phase-contiguous, lat ~29 — no pipelining needed)
        ulonglong2 xv[4];
#pragma unroll
        for (int i = 0; i < 4; ++i)
            xv[i] = *reinterpret_cast<const ulonglong2*>(xsb + i * 1024 + c * 32);

        // consume wbuf[m]
#pragma unroll
        for (int i = 0; i < 4; ++i) {
#pragma unroll
            for (int j = 0; j < 4; ++j) {
                acc[i][j] = ffma2(wbuf[m][j].x, xv[i].x, acc[i][j]);   // k0,k1
                acc[i][j] = ffma2(wbuf[m][j].y, xv[i].y, acc[i][j]);   // k2,k3
            }
        }

        // refill slot m with c+NBUF (issued ~2-3 iterations (~600-900 cyc wall)
        // before consumption -> covers DRAM latency)
        if (c + NBUF < CIN) {
            wbuf[m][0] = *reinterpret_cast<const ulonglong2*>(wr0 + (c + NBUF) * DLEN);
            wbuf[m][1] = *reinterpret_cast<const ulonglong2*>(wr1 + (c + NBUF) * DLEN);
            wbuf[m][2] = *reinterpret_cast<const ulonglong2*>(wr2 + (c + NBUF) * DLEN);
            wbuf[m][3] = *reinterpret_cast<const ulonglong2*>(wr3 + (c + NBUF) * DLEN);
        }
    }

    // ---- Epilogue ----
    const float scale = 0.17677669529663687f;   // 1/sqrt(32)
    const int p = p0 + p_l;
#pragma unroll
    for (int i = 0; i < 4; ++i)
#pragma unroll
        for (int j = 0; j < 4; ++j) {
            float2 v = *reinterpret_cast<float2*>(&acc[i][j]);
            out[(b0 + i) * (COUT * OUT_DIM) + (o0 + j) * OUT_DIM + p] =
                (v.x + v.y) * scale;
        }
}

extern "C" void kernel_launch(void* const* d_in, const int* in_sizes, int n_in,
                              void* d_out, int out_size) {
    const float* x = (const float*)d_in[0];
    const float* w = (const float*)d_in[1];
    float* out = (float*)d_out;

    // 64 KB dynamic smem (> 48 KB default). Non-stream API; idempotent; legal
    // during graph capture — called unconditionally every launch (no static guards).
    cudaFuncSetAttribute(lc1d_kernel, cudaFuncAttributeMaxDynamicSharedMemorySize,
                         SMEM_BYTES);

    lc1d_kernel<<<OUT_DIM / P_TILE, NTHREADS, SMEM_BYTES>>>(x, w, out);
}